// round 4
// baseline (speedup 1.0000x reference)
#include <cuda_runtime.h>
#include <cstdint>

#define B_SZ 256
#define T_SZ 168
#define LAG 168
#define LAT 128
#define WS 64
#define H_SZ 1024

#define KC 64
#define APITCH 68              // 68 % 32 = 4 -> conflict-free frag reads
#define A_ELEMS (128 * APITCH)
#define B_ELEMS (48 * APITCH)

// ---- device scratch (no allocations allowed) ----
__device__ float g_hbuf[2][B_SZ * H_SZ];  // ping-pong GRU state (tf32-rounded fp32)
__device__ float g_e1[B_SZ * 64];
__device__ float g_e2[B_SZ * LAT];

__device__ __forceinline__ float leakyf(float x) { return x >= 0.f ? x : 0.01f * x; }
__device__ __forceinline__ float sigmoidf_(float x) { return 1.f / (1.f + expf(-x)); }
__device__ __forceinline__ float rna_tf32(float x) {
    uint32_t o;
    asm("cvt.rna.tf32.f32 %0, %1;" : "=r"(o) : "f"(x));
    return __uint_as_float(o);
}
__device__ __forceinline__ void cp16(void* sdst, const void* gsrc) {
    uint32_t s = (uint32_t)__cvta_generic_to_shared(sdst);
    asm volatile("cp.async.cg.shared.global [%0], [%1], 16;" ::"r"(s), "l"(gsrc));
}
__device__ __forceinline__ void cp_commit() { asm volatile("cp.async.commit_group;"); }
template <int N>
__device__ __forceinline__ void cp_wait() { asm volatile("cp.async.wait_group %0;" ::"n"(N)); }

// ================= encoder MLP (tiny, fp32) =================
__global__ void enc1(const float* __restrict__ lag, const float* __restrict__ W1,
                     const float* __restrict__ b1) {
    __shared__ float row[LAG];
    int b = blockIdx.x, j = threadIdx.x;
    for (int i = j; i < LAG; i += 64) row[i] = lag[b * LAG + i];
    __syncthreads();
    float acc = b1[j];
    const float* w = W1 + j * LAG;
#pragma unroll 4
    for (int i = 0; i < LAG; ++i) acc += row[i] * w[i];
    g_e1[b * 64 + j] = leakyf(acc);
}

__global__ void enc2(const float* __restrict__ W2, const float* __restrict__ b2) {
    __shared__ float row[64];
    int b = blockIdx.x, j = threadIdx.x;
    if (j < 64) row[j] = g_e1[b * 64 + j];
    __syncthreads();
    float acc = b2[j];
    const float* w = W2 + j * 64;
#pragma unroll 8
    for (int i = 0; i < 64; ++i) acc += row[i] * w[i];
    g_e2[b * LAT + j] = leakyf(acc);
}

__global__ void enc3(const float* __restrict__ W3, const float* __restrict__ b3) {
    __shared__ float row[LAT];
    int b = blockIdx.x, tid = threadIdx.x;
    if (tid < LAT) row[tid] = g_e2[b * LAT + tid];
    __syncthreads();
#pragma unroll
    for (int rep = 0; rep < 4; ++rep) {
        int j = tid + rep * 256;
        float acc = b3[j];
        const float* w = W3 + j * LAT;
#pragma unroll 8
        for (int i = 0; i < LAT; ++i) acc += row[i] * w[i];
        g_hbuf[0][b * H_SZ + j] = rna_tf32(acc);  // h0, rounded to tf32 grid
    }
}

__global__ void init_out(float* __restrict__ out, const float* __restrict__ bo) {
    int i = blockIdx.x * 256 + threadIdx.x;
    if (i < B_SZ * T_SZ) out[i] = bo[0];
}

// ================= fused GRU step =================
// CTA tile: 128 batch rows (blockIdx.y) x 16 hidden units (blockIdx.x),
// i.e. 48 gate columns ordered [r(16) | z(16) | n(16)].
// 8 warps, each warp: 16 rows x 48 cols via 6x m16n8k8 tf32 mma frags.
// K pipeline: chunk 0 = input GEMM (x_t @ Wih.T, K=64) -> acci,
//             chunks 1..16 = hidden GEMM (h @ Whh.T, K=1024) -> acc.
__global__ void __launch_bounds__(256) gru_step(
    int t, int par,
    const float* __restrict__ curr,
    const float* __restrict__ Wih, const float* __restrict__ Whh,
    const float* __restrict__ bih, const float* __restrict__ bhh,
    const float* __restrict__ Wo, float* __restrict__ out) {
    extern __shared__ float smem[];
    float* As[2] = {smem, smem + A_ELEMS};
    float* Bs[2] = {smem + 2 * A_ELEMS, smem + 2 * A_ELEMS + B_ELEMS};

    const float* __restrict__ hprev = g_hbuf[par];
    float* __restrict__ hnext = g_hbuf[par ^ 1];

    const int tid = threadIdx.x;
    const int j0 = blockIdx.x * 16;
    const int m0 = blockIdx.y * 128;
    const float* xsrc = curr + (size_t)t * (B_SZ * WS);

    auto load_chunk = [&](int c, int buf) {
        const float* Asrc;
        const float* Bsrc;
        int lda, kb;
        if (c == 0) { Asrc = xsrc; lda = WS; Bsrc = Wih; kb = 0; }
        else        { Asrc = hprev; lda = H_SZ; Bsrc = Whh; kb = (c - 1) * KC; }
        float* Ad = As[buf];
        float* Bd = Bs[buf];
#pragma unroll
        for (int i = 0; i < 8; ++i) {  // 128 rows x 16 float4
            int idx = tid + i * 256;
            int row = idx >> 4, c4 = (idx & 15) * 4;
            cp16(Ad + row * APITCH + c4, Asrc + (size_t)(m0 + row) * lda + kb + c4);
        }
#pragma unroll
        for (int i = 0; i < 3; ++i) {  // 48 gate rows x 16 float4
            int idx = tid + i * 256;
            int rl = idx >> 4, c4 = (idx & 15) * 4;
            int g = (rl >> 4) * H_SZ + j0 + (rl & 15);
            cp16(Bd + rl * APITCH + c4, Bsrc + (size_t)g * lda + kb + c4);
        }
        cp_commit();
    };

    const int warp = tid >> 5, lane = tid & 31;
    const int gid = lane >> 2, tig = lane & 3;
    const int wrow = warp * 16;

    float acc[6][4], acci[6][4];
#pragma unroll
    for (int f = 0; f < 6; ++f)
#pragma unroll
        for (int e = 0; e < 4; ++e) { acc[f][e] = 0.f; acci[f][e] = 0.f; }

    load_chunk(0, 0);
#pragma unroll 1
    for (int c = 0; c < 17; ++c) {
        const int buf = c & 1;
        if (c + 1 < 17) { load_chunk(c + 1, (c + 1) & 1); cp_wait<1>(); }
        else            { cp_wait<0>(); }
        __syncthreads();
        const float* Ad = As[buf];
        const float* Bd = Bs[buf];
#pragma unroll
        for (int kk = 0; kk < 8; ++kk) {
            const int kc = kk * 8;
            uint32_t a0 = *(const uint32_t*)(Ad + (wrow + gid) * APITCH + kc + tig);
            uint32_t a1 = *(const uint32_t*)(Ad + (wrow + gid + 8) * APITCH + kc + tig);
            uint32_t a2 = *(const uint32_t*)(Ad + (wrow + gid) * APITCH + kc + tig + 4);
            uint32_t a3 = *(const uint32_t*)(Ad + (wrow + gid + 8) * APITCH + kc + tig + 4);
#pragma unroll
            for (int f = 0; f < 6; ++f) {
                uint32_t b0 = *(const uint32_t*)(Bd + (f * 8 + gid) * APITCH + kc + tig);
                uint32_t b1 = *(const uint32_t*)(Bd + (f * 8 + gid) * APITCH + kc + tig + 4);
                asm("mma.sync.aligned.m16n8k8.row.col.f32.tf32.tf32.f32 "
                    "{%0,%1,%2,%3}, {%4,%5,%6,%7}, {%8,%9}, {%0,%1,%2,%3};"
                    : "+f"(acc[f][0]), "+f"(acc[f][1]), "+f"(acc[f][2]), "+f"(acc[f][3])
                    : "r"(a0), "r"(a1), "r"(a2), "r"(a3), "r"(b0), "r"(b1));
            }
        }
        __syncthreads();  // protect buf before it is re-filled two chunks later
        if (c == 0) {
#pragma unroll
            for (int f = 0; f < 6; ++f)
#pragma unroll
                for (int e = 0; e < 4; ++e) { acci[f][e] = acc[f][e]; acc[f][e] = 0.f; }
        }
    }

    // ---- fused GRU gate epilogue + output head ----
    const int bbase = m0 + wrow + gid;
    float psum0 = 0.f, psum1 = 0.f;
#pragma unroll
    for (int f2 = 0; f2 < 2; ++f2) {
#pragma unroll
        for (int cs = 0; cs < 2; ++cs) {
            const int u = f2 * 8 + 2 * tig + cs;
            const int j = j0 + u;
            const float bir = bih[j] + bhh[j];
            const float biz = bih[H_SZ + j] + bhh[H_SZ + j];
            const float bin = bih[2 * H_SZ + j];
            const float bhn = bhh[2 * H_SZ + j];
            const float wo = Wo[j];
#pragma unroll
            for (int rs = 0; rs < 2; ++rs) {
                const int e = rs * 2 + cs;
                const int b = bbase + rs * 8;
                float r = sigmoidf_(acci[f2][e] + acc[f2][e] + bir);
                float z = sigmoidf_(acci[2 + f2][e] + acc[2 + f2][e] + biz);
                float n = tanhf(acci[4 + f2][e] + bin + r * (acc[4 + f2][e] + bhn));
                float hold = hprev[(size_t)b * H_SZ + j];
                float hv = (1.f - z) * n + z * hold;
                hnext[(size_t)b * H_SZ + j] = rna_tf32(hv);
                float p = hv * wo;
                if (rs == 0) psum0 += p; else psum1 += p;
            }
        }
    }
    // reduce the 4 lanes (tig 0..3) that share the same batch rows
    psum0 += __shfl_xor_sync(0xffffffffu, psum0, 1);
    psum0 += __shfl_xor_sync(0xffffffffu, psum0, 2);
    psum1 += __shfl_xor_sync(0xffffffffu, psum1, 1);
    psum1 += __shfl_xor_sync(0xffffffffu, psum1, 2);
    if (tig == 0) {
        atomicAdd(out + (size_t)bbase * T_SZ + t, psum0);
        atomicAdd(out + (size_t)(bbase + 8) * T_SZ + t, psum1);
    }
}

// ================= launch =================
extern "C" void kernel_launch(void* const* d_in, const int* in_sizes, int n_in,
                              void* d_out, int out_size) {
    const float* lag  = (const float*)d_in[0];
    const float* curr = (const float*)d_in[1];
    const float* W1   = (const float*)d_in[2];
    const float* b1   = (const float*)d_in[3];
    const float* W2   = (const float*)d_in[4];
    const float* b2   = (const float*)d_in[5];
    const float* W3   = (const float*)d_in[6];
    const float* b3   = (const float*)d_in[7];
    const float* Wih  = (const float*)d_in[8];
    const float* Whh  = (const float*)d_in[9];
    const float* bih  = (const float*)d_in[10];
    const float* bhh  = (const float*)d_in[11];
    const float* Wo   = (const float*)d_in[12];
    const float* bo   = (const float*)d_in[13];
    float* out = (float*)d_out;

    const size_t SMEM = (size_t)(2 * A_ELEMS + 2 * B_ELEMS) * sizeof(float);  // ~93.5 KB
    cudaFuncSetAttribute(gru_step, cudaFuncAttributeMaxDynamicSharedMemorySize, (int)SMEM);

    init_out<<<(B_SZ * T_SZ + 255) / 256, 256>>>(out, bo);
    enc1<<<B_SZ, 64>>>(lag, W1, b1);
    enc2<<<B_SZ, LAT>>>(W2, b2);
    enc3<<<B_SZ, 256>>>(W3, b3);

    dim3 grid(64, 2);
    for (int t = 0; t < T_SZ; ++t) {
        gru_step<<<grid, 256, SMEM>>>(t, t & 1, curr, Wih, Whh, bih, bhh, Wo, out);
    }
}

// round 5
// speedup vs baseline: 1.2317x; 1.2317x over previous
#include <cuda_runtime.h>
#include <cstdint>

#define B_SZ 256
#define T_SZ 168
#define LAG 168
#define LAT 128
#define WS 64
#define H_SZ 1024

#define KC 64
#define NCHUNK 17
#define PITCH 68                 // 68 % 32 == 4 -> conflict-free frag reads
#define A_ROWS 64
#define B_ROWS 96
#define STAGE_FLOATS ((A_ROWS + B_ROWS) * PITCH)   // 10880 floats / stage
#define GRID_CTAS 128
#define NTHREADS 128

// ---- device scratch (no allocations allowed) ----
__device__ float g_hbuf[2][B_SZ * H_SZ];   // ping-pong GRU state
__device__ float g_e1[B_SZ * 64];
__device__ float g_e2[B_SZ * LAT];
__device__ unsigned g_cnt;                 // grid barrier arrivals (monotonic per launch)
__device__ unsigned g_gen;                 // grid barrier generation

__device__ __forceinline__ float leakyf(float x) { return x >= 0.f ? x : 0.01f * x; }
__device__ __forceinline__ float sigmoidf_(float x) { return 1.f / (1.f + expf(-x)); }
__device__ __forceinline__ float rna_tf32(float x) {
    uint32_t o;
    asm("cvt.rna.tf32.f32 %0, %1;" : "=r"(o) : "f"(x));
    return __uint_as_float(o);
}
__device__ __forceinline__ void cp16(void* sdst, const void* gsrc) {
    uint32_t s = (uint32_t)__cvta_generic_to_shared(sdst);
    asm volatile("cp.async.cg.shared.global [%0], [%1], 16;" ::"r"(s), "l"(gsrc));
}
__device__ __forceinline__ void cp_commit() { asm volatile("cp.async.commit_group;"); }
template <int N>
__device__ __forceinline__ void cp_wait() { asm volatile("cp.async.wait_group %0;" ::"n"(N)); }

// ================= encoder MLP =================
__global__ void enc1(const float* __restrict__ lag, const float* __restrict__ W1,
                     const float* __restrict__ b1) {
    __shared__ float row[LAG];
    int b = blockIdx.x, j = threadIdx.x;
    for (int i = j; i < LAG; i += 64) row[i] = lag[b * LAG + i];
    __syncthreads();
    float acc = b1[j];
    const float* w = W1 + j * LAG;
#pragma unroll 4
    for (int i = 0; i < LAG; ++i) acc += row[i] * w[i];
    g_e1[b * 64 + j] = leakyf(acc);
}

__global__ void enc2(const float* __restrict__ W2, const float* __restrict__ b2) {
    __shared__ float row[64];
    int b = blockIdx.x, j = threadIdx.x;
    if (j < 64) row[j] = g_e1[b * 64 + j];
    __syncthreads();
    float acc = b2[j];
    const float* w = W2 + j * 64;
#pragma unroll 8
    for (int i = 0; i < 64; ++i) acc += row[i] * w[i];
    g_e2[b * LAT + j] = leakyf(acc);
}

// enc3: block = (16 batch rows) x (128 hidden cols); W3 row reused for 8 batches.
__global__ void enc3(const float* __restrict__ W3, const float* __restrict__ b3) {
    __shared__ float sm[16][LAT];
    int bg = blockIdx.x;      // 0..15 batch group
    int jg = blockIdx.y;      // 0..7 col group
    int tid = threadIdx.x;
    for (int i = tid; i < 16 * LAT; i += 256)
        sm[i >> 7][i & 127] = g_e2[(bg * 16 + (i >> 7)) * LAT + (i & 127)];
    __syncthreads();
    int j = jg * 128 + (tid & 127);
    int bs = (tid >> 7) * 8;  // 0 or 8
    float acc[8];
#pragma unroll
    for (int i = 0; i < 8; ++i) acc[i] = b3[j];
    const float* w = W3 + (size_t)j * LAT;
    for (int k = 0; k < LAT; ++k) {
        float wv = w[k];
#pragma unroll
        for (int i = 0; i < 8; ++i) acc[i] += sm[bs + i][k] * wv;
    }
#pragma unroll
    for (int i = 0; i < 8; ++i)
        g_hbuf[0][(size_t)(bg * 16 + bs + i) * H_SZ + j] = rna_tf32(acc[i]);
}

__global__ void init_all(float* __restrict__ out, const float* __restrict__ bo) {
    int i = blockIdx.x * 256 + threadIdx.x;
    if (i == 0) { g_cnt = 0u; g_gen = 0u; }
    if (i < B_SZ * T_SZ) out[i] = bo[0];
}

// ================= persistent fused GRU =================
// grid = 128 CTAs: 4 m-tiles (64 batch rows) x 32 n-tiles (32 hidden units).
// CTA gate-column layout (96 cols): [grp0: r16 z16 n16][grp1: r16 z16 n16].
// 4 warps (2m x 2n), warp tile 32 rows x 48 cols, tf32 m16n8k8 mma.
// Per step: chunk 0 = input GEMM (x_t @ Wih.T) -> acci, chunks 1..16 = h @ Whh.T.
// 3-stage cp.async pipeline, one __syncthreads per chunk, grid barrier per step.
__global__ void __launch_bounds__(NTHREADS, 1) gru_persist(
    const float* __restrict__ curr, const float* __restrict__ Wih,
    const float* __restrict__ Whh, const float* __restrict__ bih,
    const float* __restrict__ bhh, const float* __restrict__ Wo,
    float* __restrict__ out) {
    extern __shared__ float smem[];
    const int tid = threadIdx.x;
    const int warp = tid >> 5, lane = tid & 31;
    const int gid = lane >> 2, tig = lane & 3;
    const int wm = warp & 1, wn = warp >> 1;
    const int wrow = wm * 32;         // warp's row base within CTA
    const int cb = wn * 48;           // warp's col base within B tile
    const int nt = blockIdx.x & 31, mt = blockIdx.x >> 5;
    const int m0 = mt * 64;
    const int jb0 = nt * 32;
    const int jbase = jb0 + wn * 16;

    // hoisted per-thread biases / head weights (t-invariant)
    float bir[2][2], biz[2][2], bin_[2][2], bhn_[2][2], wo_[2][2];
#pragma unroll
    for (int fh = 0; fh < 2; ++fh)
#pragma unroll
        for (int cs = 0; cs < 2; ++cs) {
            int j = jbase + 8 * fh + 2 * tig + cs;
            bir[fh][cs] = bih[j] + bhh[j];
            biz[fh][cs] = bih[H_SZ + j] + bhh[H_SZ + j];
            bin_[fh][cs] = bih[2 * H_SZ + j];
            bhn_[fh][cs] = bhh[2 * H_SZ + j];
            wo_[fh][cs] = Wo[j];
        }

    const float* hprev = g_hbuf[0];

    auto load_chunk = [&](int c, int s, int tt) {
        float* Ad = smem + s * STAGE_FLOATS;
        float* Bd = Ad + A_ROWS * PITCH;
        const float *Asrc, *Bsrc;
        int lda, kb;
        if (c == 0) { Asrc = curr + (size_t)tt * (B_SZ * WS) + (size_t)m0 * WS; lda = WS; Bsrc = Wih; kb = 0; }
        else        { Asrc = hprev + (size_t)m0 * H_SZ; lda = H_SZ; Bsrc = Whh; kb = (c - 1) * KC; }
#pragma unroll
        for (int i = 0; i < 8; ++i) {  // A: 64 rows x 16 float4
            int idx = tid + i * NTHREADS;
            int row = idx >> 4, c4 = (idx & 15) * 4;
            cp16(Ad + row * PITCH + c4, Asrc + (size_t)row * lda + kb + c4);
        }
#pragma unroll
        for (int i = 0; i < 12; ++i) { // B: 96 gate rows x 16 float4
            int idx = tid + i * NTHREADS;
            int rl = idx >> 4, c4 = (idx & 15) * 4;
            int grp = rl / 48, rem = rl - grp * 48;
            int gate = rem >> 4, unit = rem & 15;
            int grow = gate * H_SZ + jb0 + grp * 16 + unit;
            cp16(Bd + rl * PITCH + c4, Bsrc + (size_t)grow * lda + kb + c4);
        }
        cp_commit();
    };

    float acc[2][6][4], acci[2][6][4];

    load_chunk(0, 0, 0);  // prefetch chunk 0 of t = 0

    for (int t = 0; t < T_SZ; ++t) {
        hprev = g_hbuf[t & 1];
        float* hnext = g_hbuf[(t + 1) & 1];

#pragma unroll
        for (int mf = 0; mf < 2; ++mf)
#pragma unroll
            for (int f = 0; f < 6; ++f)
#pragma unroll
                for (int e = 0; e < 4; ++e) acc[mf][f][e] = 0.f;

        load_chunk(1, 1, t);

#pragma unroll 1
        for (int c = 0; c < NCHUNK; ++c) {
            if (c < NCHUNK - 1) cp_wait<1>(); else cp_wait<0>();
            __syncthreads();
            if (c + 2 < NCHUNK) load_chunk(c + 2, (c + 2) % 3, t);
            const float* Ad = smem + (c % 3) * STAGE_FLOATS;
            const float* Bd = Ad + A_ROWS * PITCH;
#pragma unroll
            for (int kk = 0; kk < 8; ++kk) {
                const int kc = kk * 8;
                uint32_t a[2][4];
#pragma unroll
                for (int mf = 0; mf < 2; ++mf) {
                    const float* p = Ad + (wrow + 16 * mf + gid) * PITCH + kc + tig;
                    a[mf][0] = __float_as_uint(p[0]);
                    a[mf][1] = __float_as_uint(p[8 * PITCH]);
                    a[mf][2] = __float_as_uint(p[4]);
                    a[mf][3] = __float_as_uint(p[8 * PITCH + 4]);
                }
#pragma unroll
                for (int f = 0; f < 6; ++f) {
                    const float* q = Bd + (cb + 8 * f + gid) * PITCH + kc + tig;
                    uint32_t b0 = __float_as_uint(q[0]);
                    uint32_t b1 = __float_as_uint(q[4]);
#pragma unroll
                    for (int mf = 0; mf < 2; ++mf) {
                        asm("mma.sync.aligned.m16n8k8.row.col.f32.tf32.tf32.f32 "
                            "{%0,%1,%2,%3}, {%4,%5,%6,%7}, {%8,%9}, {%0,%1,%2,%3};"
                            : "+f"(acc[mf][f][0]), "+f"(acc[mf][f][1]),
                              "+f"(acc[mf][f][2]), "+f"(acc[mf][f][3])
                            : "r"(a[mf][0]), "r"(a[mf][1]), "r"(a[mf][2]), "r"(a[mf][3]),
                              "r"(b0), "r"(b1));
                    }
                }
            }
            if (c == 0) {
#pragma unroll
                for (int mf = 0; mf < 2; ++mf)
#pragma unroll
                    for (int f = 0; f < 6; ++f)
#pragma unroll
                        for (int e = 0; e < 4; ++e) { acci[mf][f][e] = acc[mf][f][e]; acc[mf][f][e] = 0.f; }
            }
        }

        // ---- fused GRU gate epilogue + output head ----
        float ps[4] = {0.f, 0.f, 0.f, 0.f};
#pragma unroll
        for (int mf = 0; mf < 2; ++mf)
#pragma unroll
            for (int fh = 0; fh < 2; ++fh)
#pragma unroll
                for (int cs = 0; cs < 2; ++cs) {
                    int j = jbase + 8 * fh + 2 * tig + cs;
#pragma unroll
                    for (int rs = 0; rs < 2; ++rs) {
                        int e = rs * 2 + cs;
                        int b = m0 + wrow + 16 * mf + gid + 8 * rs;
                        float r = sigmoidf_(acci[mf][fh][e] + acc[mf][fh][e] + bir[fh][cs]);
                        float z = sigmoidf_(acci[mf][2 + fh][e] + acc[mf][2 + fh][e] + biz[fh][cs]);
                        float n = tanhf(acci[mf][4 + fh][e] + bin_[fh][cs] +
                                        r * (acc[mf][4 + fh][e] + bhn_[fh][cs]));
                        float hold = hprev[b * H_SZ + j];
                        float hv = (1.f - z) * n + z * hold;
                        hnext[b * H_SZ + j] = rna_tf32(hv);
                        ps[mf * 2 + rs] += hv * wo_[fh][cs];
                    }
                }
#pragma unroll
        for (int i = 0; i < 4; ++i) {
            ps[i] += __shfl_xor_sync(0xffffffffu, ps[i], 1);
            ps[i] += __shfl_xor_sync(0xffffffffu, ps[i], 2);
        }
        if (tig == 0) {
#pragma unroll
            for (int i = 0; i < 4; ++i) {
                int b = m0 + wrow + 16 * (i >> 1) + gid + 8 * (i & 1);
                atomicAdd(out + b * T_SZ + t, ps[i]);
            }
        }

        if (t + 1 < T_SZ) {
            load_chunk(0, 0, t + 1);  // x/Wih prefetch: no h dependency, overlaps barrier

            // ---- grid barrier ----
            __threadfence();
            __syncthreads();
            if (tid == 0) {
                unsigned prev = atomicAdd(&g_cnt, 1u);
                if (prev == (unsigned)GRID_CTAS * (unsigned)(t + 1) - 1u) {
                    __threadfence();
                    *(volatile unsigned*)&g_gen = (unsigned)(t + 1);
                } else {
                    while (*(volatile unsigned*)&g_gen < (unsigned)(t + 1)) {}
                }
                __threadfence();
            }
            __syncthreads();
        }
    }
}

// ================= launch =================
extern "C" void kernel_launch(void* const* d_in, const int* in_sizes, int n_in,
                              void* d_out, int out_size) {
    const float* lag  = (const float*)d_in[0];
    const float* curr = (const float*)d_in[1];
    const float* W1   = (const float*)d_in[2];
    const float* b1   = (const float*)d_in[3];
    const float* W2   = (const float*)d_in[4];
    const float* b2   = (const float*)d_in[5];
    const float* W3   = (const float*)d_in[6];
    const float* b3   = (const float*)d_in[7];
    const float* Wih  = (const float*)d_in[8];
    const float* Whh  = (const float*)d_in[9];
    const float* bih  = (const float*)d_in[10];
    const float* bhh  = (const float*)d_in[11];
    const float* Wo   = (const float*)d_in[12];
    const float* bo   = (const float*)d_in[13];
    float* out = (float*)d_out;

    const size_t SMEM = (size_t)(3 * STAGE_FLOATS) * sizeof(float);  // 130560 B
    cudaFuncSetAttribute(gru_persist, cudaFuncAttributeMaxDynamicSharedMemorySize, (int)SMEM);

    init_all<<<(B_SZ * T_SZ + 255) / 256, 256>>>(out, bo);
    enc1<<<B_SZ, 64>>>(lag, W1, b1);
    enc2<<<B_SZ, LAT>>>(W2, b2);
    dim3 g3(16, 8);
    enc3<<<g3, 256>>>(W3, b3);

    gru_persist<<<GRID_CTAS, NTHREADS, SMEM>>>(curr, Wih, Whh, bih, bhh, Wo, out);
}

// round 6
// speedup vs baseline: 1.3563x; 1.1012x over previous
#include <cuda_runtime.h>
#include <cstdint>

#define B_SZ 256
#define T_SZ 168
#define LAG 168
#define LAT 128
#define WS 64
#define H_SZ 1024

#define KC 64
#define PITCH 68                 // 68 % 32 == 4 -> conflict-free frag reads
#define A_ROWS 64
#define B_ROWS 96
#define STAGE_FLOATS ((A_ROWS + B_ROWS) * PITCH)   // 10880 floats / stage
#define RED_PITCH 52
#define GRID_CTAS 128
#define NTHREADS 256

// ---- device scratch (no allocations allowed) ----
__device__ float g_hbuf[2][B_SZ * H_SZ];   // ping-pong GRU state
__device__ float g_e2[B_SZ * LAT];
__device__ unsigned g_cnt;                 // grid barrier arrivals
__device__ unsigned g_gen;                 // grid barrier generation

__device__ __forceinline__ float leakyf(float x) { return x >= 0.f ? x : 0.01f * x; }
__device__ __forceinline__ float sigmoidf_(float x) { return 1.f / (1.f + expf(-x)); }
__device__ __forceinline__ float rna_tf32(float x) {
    uint32_t o;
    asm("cvt.rna.tf32.f32 %0, %1;" : "=r"(o) : "f"(x));
    return __uint_as_float(o);
}
__device__ __forceinline__ void cp16(void* sdst, const void* gsrc) {
    uint32_t s = (uint32_t)__cvta_generic_to_shared(sdst);
    asm volatile("cp.async.cg.shared.global [%0], [%1], 16;" ::"r"(s), "l"(gsrc));
}
__device__ __forceinline__ void cp_commit() { asm volatile("cp.async.commit_group;"); }
template <int N>
__device__ __forceinline__ void cp_wait() { asm volatile("cp.async.wait_group %0;" ::"n"(N)); }

#define BAR_ALL() asm volatile("bar.sync 0, 256;" ::: "memory")
#define BAR_G0()  asm volatile("bar.sync 1, 128;" ::: "memory")
#define BAR_G1()  asm volatile("bar.sync 2, 128;" ::: "memory")

// ================= fused: out-init + enc1 + enc2 =================
__global__ void fused_pre(const float* __restrict__ lag, const float* __restrict__ W1,
                          const float* __restrict__ b1, const float* __restrict__ W2,
                          const float* __restrict__ b2, const float* __restrict__ bo,
                          float* __restrict__ out) {
    __shared__ float row[LAG];
    __shared__ float e1[64];
    int b = blockIdx.x, tid = threadIdx.x;
    if (b == 0 && tid == 0) { g_cnt = 0u; g_gen = 0u; }
    float bov = bo[0];
    for (int t = tid; t < T_SZ; t += 128) out[b * T_SZ + t] = bov;
    for (int i = tid; i < LAG; i += 128) row[i] = lag[b * LAG + i];
    __syncthreads();
    if (tid < 64) {
        float acc = b1[tid];
        const float* w = W1 + tid * LAG;
#pragma unroll 4
        for (int i = 0; i < LAG; ++i) acc += row[i] * w[i];
        e1[tid] = leakyf(acc);
    }
    __syncthreads();
    float acc = b2[tid];
    const float* w = W2 + tid * 64;
#pragma unroll 8
    for (int i = 0; i < 64; ++i) acc += e1[i] * w[i];
    g_e2[b * LAT + tid] = leakyf(acc);
}

// enc3: block = (16 batch rows) x (128 hidden cols); W3 row reused for 8 batches.
__global__ void enc3(const float* __restrict__ W3, const float* __restrict__ b3) {
    __shared__ float sm[16][LAT];
    int bg = blockIdx.x, jg = blockIdx.y, tid = threadIdx.x;
    for (int i = tid; i < 16 * LAT; i += 256)
        sm[i >> 7][i & 127] = g_e2[(bg * 16 + (i >> 7)) * LAT + (i & 127)];
    __syncthreads();
    int j = jg * 128 + (tid & 127);
    int bs = (tid >> 7) * 8;
    float acc[8];
#pragma unroll
    for (int i = 0; i < 8; ++i) acc[i] = b3[j];
    const float* w = W3 + (size_t)j * LAT;
    for (int k = 0; k < LAT; ++k) {
        float wv = w[k];
#pragma unroll
        for (int i = 0; i < 8; ++i) acc[i] += sm[bs + i][k] * wv;
    }
#pragma unroll
    for (int i = 0; i < 8; ++i)
        g_hbuf[0][(size_t)(bg * 16 + bs + i) * H_SZ + j] = rna_tf32(acc[i]);
}

// ================= persistent fused GRU, K-split warp groups =================
// grid = 128 CTAs = 4 m-tiles (64 batch rows) x 32 n-tiles (32 hidden units).
// 8 warps: warps 0-3 = K-group 0 (input chunk + hidden K 0..447, stages 0/1),
//          warps 4-7 = K-group 1 (hidden K 448..1023, stages 2/3).
// Each group: 4 warps in 2m x 2n, warp tile 32 rows x 48 gate cols, tf32 mma.
// Group 1 passes partials through smem; group 0 does gates + head + h write.
__global__ void __launch_bounds__(NTHREADS, 1) gru_persist(
    const float* __restrict__ curr, const float* __restrict__ Wih,
    const float* __restrict__ Whh, const float* __restrict__ bih,
    const float* __restrict__ bhh, const float* __restrict__ Wo,
    float* __restrict__ out) {
    extern __shared__ float smem[];
    float* red = smem + 3 * STAGE_FLOATS;  // reuses stage-3 region (free at exchange time)

    const int tid = threadIdx.x;
    const int warp = tid >> 5, lane = tid & 31;
    const int gid = lane >> 2, tig = lane & 3;
    const int grp = warp >> 2;       // K-group
    const int wi = warp & 3;
    const int wm = wi & 1, wn = wi >> 1;
    const int wrow = wm * 32;
    const int cb = wn * 48;
    const int tidg = tid & 127;
    const int nt = blockIdx.x & 31, mt = blockIdx.x >> 5;
    const int m0 = mt * 64;
    const int jb0 = nt * 32;
    const int jbase = jb0 + wn * 16;

    // hoisted biases / head weights (group 0 epilogue only, but computed uniformly)
    float bir[2][2], biz[2][2], bin_[2][2], bhn_[2][2], wo_[2][2];
#pragma unroll
    for (int fh = 0; fh < 2; ++fh)
#pragma unroll
        for (int cs = 0; cs < 2; ++cs) {
            int j = jbase + 8 * fh + 2 * tig + cs;
            bir[fh][cs] = bih[j] + bhh[j];
            biz[fh][cs] = bih[H_SZ + j] + bhh[H_SZ + j];
            bin_[fh][cs] = bih[2 * H_SZ + j];
            bhn_[fh][cs] = bhh[2 * H_SZ + j];
            wo_[fh][cs] = Wo[j];
        }

    auto load_chunk = [&](const float* Asrc, int lda, int kb, const float* Bsrc, int s) {
        float* Ad = smem + s * STAGE_FLOATS;
        float* Bd = Ad + A_ROWS * PITCH;
#pragma unroll
        for (int i = 0; i < 8; ++i) {
            int idx = tidg + i * 128;
            int r = idx >> 4, c4 = (idx & 15) * 4;
            cp16(Ad + r * PITCH + c4, Asrc + (size_t)r * lda + kb + c4);
        }
#pragma unroll
        for (int i = 0; i < 12; ++i) {
            int idx = tidg + i * 128;
            int rl = idx >> 4, c4 = (idx & 15) * 4;
            int gg = rl / 48, rem = rl - gg * 48;
            int gate = rem >> 4, unit = rem & 15;
            int grow = gate * H_SZ + jb0 + gg * 16 + unit;
            cp16(Bd + rl * PITCH + c4, Bsrc + (size_t)grow * lda + kb + c4);
        }
        cp_commit();
    };

    float acc[2][6][4], acci[2][6][4];

    auto compute = [&](int s) {
        const float* Ad = smem + s * STAGE_FLOATS;
        const float* Bd = Ad + A_ROWS * PITCH;
#pragma unroll
        for (int kk = 0; kk < 8; ++kk) {
            const int kc = kk * 8;
            uint32_t a[2][4];
#pragma unroll
            for (int mf = 0; mf < 2; ++mf) {
                const float* p = Ad + (wrow + 16 * mf + gid) * PITCH + kc + tig;
                a[mf][0] = __float_as_uint(p[0]);
                a[mf][1] = __float_as_uint(p[8 * PITCH]);
                a[mf][2] = __float_as_uint(p[4]);
                a[mf][3] = __float_as_uint(p[8 * PITCH + 4]);
            }
#pragma unroll
            for (int f = 0; f < 6; ++f) {
                const float* q = Bd + (cb + 8 * f + gid) * PITCH + kc + tig;
                uint32_t b0 = __float_as_uint(q[0]);
                uint32_t b1 = __float_as_uint(q[4]);
#pragma unroll
                for (int mf = 0; mf < 2; ++mf) {
                    asm("mma.sync.aligned.m16n8k8.row.col.f32.tf32.tf32.f32 "
                        "{%0,%1,%2,%3}, {%4,%5,%6,%7}, {%8,%9}, {%0,%1,%2,%3};"
                        : "+f"(acc[mf][f][0]), "+f"(acc[mf][f][1]),
                          "+f"(acc[mf][f][2]), "+f"(acc[mf][f][3])
                        : "r"(a[mf][0]), "r"(a[mf][1]), "r"(a[mf][2]), "r"(a[mf][3]),
                          "r"(b0), "r"(b1));
                }
            }
        }
    };

    if (grp == 0)  // prefetch input chunk of t = 0 into stage 0
        load_chunk(curr + (size_t)m0 * WS, WS, 0, Wih, 0);

    for (int t = 0; t < T_SZ; ++t) {
        const float* hprev = g_hbuf[t & 1];
        float* hnext = g_hbuf[(t + 1) & 1];
        const float* Ah = hprev + (size_t)m0 * H_SZ;

#pragma unroll
        for (int mf = 0; mf < 2; ++mf)
#pragma unroll
            for (int f = 0; f < 6; ++f)
#pragma unroll
                for (int e = 0; e < 4; ++e) acc[mf][f][e] = 0.f;

        if (grp == 0) {
            // ---- group 0: input chunk + hidden chunks k=0..383 (stages 0/1) ----
            load_chunk(Ah, H_SZ, 0, Whh, 1);  // chunk 1
#pragma unroll 1
            for (int i = 0; i < 8; ++i) {
                cp_wait<1>();
                BAR_G0();
                compute(i & 1);
                if (i == 0) {
#pragma unroll
                    for (int mf = 0; mf < 2; ++mf)
#pragma unroll
                        for (int f = 0; f < 6; ++f)
#pragma unroll
                            for (int e = 0; e < 4; ++e) { acci[mf][f][e] = acc[mf][f][e]; acc[mf][f][e] = 0.f; }
                }
                BAR_G0();  // all lanes done reading this stage
                if (i < 6) {
                    load_chunk(Ah, H_SZ, (i + 1) * KC, Whh, i & 1);
                } else if (i == 6) {
                    int tn = (t + 1 < T_SZ) ? t + 1 : t;  // dummy reload on last step
                    load_chunk(curr + (size_t)tn * (B_SZ * WS) + (size_t)m0 * WS, WS, 0, Wih, 0);
                }
            }

            BAR_ALL();  // group 1's partials are in red
            {
                float* a = &acc[0][0][0];
#pragma unroll
                for (int q = 0; q < 12; ++q) {
                    float4 v = *(const float4*)(red + tidg * RED_PITCH + q * 4);
                    a[q * 4 + 0] += v.x; a[q * 4 + 1] += v.y;
                    a[q * 4 + 2] += v.z; a[q * 4 + 3] += v.w;
                }
            }

            // ---- gates + head + state write ----
            float ps[4] = {0.f, 0.f, 0.f, 0.f};
#pragma unroll
            for (int mf = 0; mf < 2; ++mf)
#pragma unroll
                for (int fh = 0; fh < 2; ++fh)
#pragma unroll
                    for (int cs = 0; cs < 2; ++cs) {
                        int j = jbase + 8 * fh + 2 * tig + cs;
#pragma unroll
                        for (int rs = 0; rs < 2; ++rs) {
                            int e = rs * 2 + cs;
                            int b = m0 + wrow + 16 * mf + gid + 8 * rs;
                            float r = sigmoidf_(acci[mf][fh][e] + acc[mf][fh][e] + bir[fh][cs]);
                            float z = sigmoidf_(acci[mf][2 + fh][e] + acc[mf][2 + fh][e] + biz[fh][cs]);
                            float n = tanhf(acci[mf][4 + fh][e] + bin_[fh][cs] +
                                            r * (acc[mf][4 + fh][e] + bhn_[fh][cs]));
                            float hold = hprev[b * H_SZ + j];
                            float hv = (1.f - z) * n + z * hold;
                            hnext[b * H_SZ + j] = rna_tf32(hv);
                            ps[mf * 2 + rs] += hv * wo_[fh][cs];
                        }
                    }
#pragma unroll
            for (int i = 0; i < 4; ++i) {
                ps[i] += __shfl_xor_sync(0xffffffffu, ps[i], 1);
                ps[i] += __shfl_xor_sync(0xffffffffu, ps[i], 2);
            }
            if (tig == 0) {
#pragma unroll
                for (int i = 0; i < 4; ++i) {
                    int b = m0 + wrow + 16 * (i >> 1) + gid + 8 * (i & 1);
                    atomicAdd(out + b * T_SZ + t, ps[i]);
                }
            }

            if (t + 1 < T_SZ) {
                __threadfence();
                BAR_ALL();
                if (tid == 0) {
                    unsigned prev = atomicAdd(&g_cnt, 1u);
                    if (prev == (unsigned)GRID_CTAS * (unsigned)(t + 1) - 1u) {
                        __threadfence();
                        *(volatile unsigned*)&g_gen = (unsigned)(t + 1);
                    } else {
                        while (*(volatile unsigned*)&g_gen < (unsigned)(t + 1)) {}
                    }
                    __threadfence();
                }
                BAR_ALL();
            }
        } else {
            // ---- group 1: hidden chunks k=448..960 (stages 2/3) ----
            load_chunk(Ah, H_SZ, 7 * KC, Whh, 2);   // chunk 8
            load_chunk(Ah, H_SZ, 8 * KC, Whh, 3);   // chunk 9
#pragma unroll 1
            for (int i = 0; i < 9; ++i) {
                if (i < 8) cp_wait<1>(); else cp_wait<0>();
                BAR_G1();
                compute(2 + (i & 1));
                BAR_G1();
                if (i < 7) load_chunk(Ah, H_SZ, (9 + i) * KC, Whh, 2 + (i & 1));
            }
            {   // export partials (stage-3 region is fully consumed by now)
                const float* a = &acc[0][0][0];
#pragma unroll
                for (int q = 0; q < 12; ++q) {
                    float4 v = make_float4(a[q * 4 + 0], a[q * 4 + 1], a[q * 4 + 2], a[q * 4 + 3]);
                    *(float4*)(red + tidg * RED_PITCH + q * 4) = v;
                }
            }
            BAR_ALL();  // partials ready for group 0

            if (t + 1 < T_SZ) {
                BAR_ALL();  // matches group 0's post-epilogue barrier
                BAR_ALL();  // matches grid-barrier release
            }
        }
    }
    cp_wait<0>();  // drain the final dummy prefetch
}

// ================= launch =================
extern "C" void kernel_launch(void* const* d_in, const int* in_sizes, int n_in,
                              void* d_out, int out_size) {
    const float* lag  = (const float*)d_in[0];
    const float* curr = (const float*)d_in[1];
    const float* W1   = (const float*)d_in[2];
    const float* b1   = (const float*)d_in[3];
    const float* W2   = (const float*)d_in[4];
    const float* b2   = (const float*)d_in[5];
    const float* W3   = (const float*)d_in[6];
    const float* b3   = (const float*)d_in[7];
    const float* Wih  = (const float*)d_in[8];
    const float* Whh  = (const float*)d_in[9];
    const float* bih  = (const float*)d_in[10];
    const float* bhh  = (const float*)d_in[11];
    const float* Wo   = (const float*)d_in[12];
    const float* bo   = (const float*)d_in[13];
    float* out = (float*)d_out;

    const size_t SMEM = (size_t)(4 * STAGE_FLOATS) * sizeof(float);  // 174080 B
    cudaFuncSetAttribute(gru_persist, cudaFuncAttributeMaxDynamicSharedMemorySize, (int)SMEM);

    fused_pre<<<B_SZ, 128>>>(lag, W1, b1, W2, b2, bo, out);
    dim3 g3(16, 8);
    enc3<<<g3, 256>>>(W3, b3);
    gru_persist<<<GRID_CTAS, NTHREADS, SMEM>>>(curr, Wih, Whh, bih, bhh, Wo, out);
}